// round 1
// baseline (speedup 1.0000x reference)
#include <cuda_runtime.h>
#include <cuda_bf16.h>
#include <math.h>

#define NN   50000
#define EE   800000
#define ET   (EE + NN)    // edges + self loops = 850000
#define INC  128
#define HC   256          // HEADS*HID
#define OUTC 40
#define NEG  0.2f

// ---------------- device scratch (no allocations allowed) ----------------
__device__ float g_bufH[(size_t)NN * HC];   // linear output of current layer
__device__ float g_bufA[(size_t)NN * HC];   // aggregated output / next input
__device__ float g_als[(size_t)NN * 4];
__device__ float g_ald[(size_t)NN * 4];
__device__ float g_attn[(size_t)ET * 4];    // per-edge attention scratch
__device__ float g_rden[(size_t)NN * 4];
__device__ int   g_off[NN + 1];
__device__ int   g_cur[NN];
__device__ int   g_deg[NN];
__device__ int   g_csr[ET];
__device__ int   g_bsum[64];
__device__ int   g_i64flag;

// ---------------- edge dtype detection (int64 vs int32) -------------------
__global__ void k_detect(const int* ei32) {
    __shared__ int any;
    if (threadIdx.x == 0) any = 0;
    __syncthreads();
    int bad = 0;
    for (int i = threadIdx.x; i < 4096; i += blockDim.x)
        if (ei32[2 * i + 1] != 0) bad = 1;
    if (bad) any = 1;
    __syncthreads();
    if (threadIdx.x == 0) g_i64flag = any ? 0 : 1;
}

__device__ __forceinline__ int edge_at(const void* ei, int f, long long pos) {
    return f ? (int)(((const long long*)ei)[pos]) : ((const int*)ei)[pos];
}

// ---------------- CSR build ----------------
__global__ void k_zero() {
    int i = blockIdx.x * blockDim.x + threadIdx.x;
    if (i < NN) { g_deg[i] = 0; g_cur[i] = 0; }
}

__global__ void k_hist(const void* ei) {
    int e = blockIdx.x * blockDim.x + threadIdx.x;
    if (e >= ET) return;
    int f = g_i64flag;
    int d = (e < EE) ? edge_at(ei, f, (long long)EE + e) : (e - EE);
    atomicAdd(&g_deg[d], 1);
}

#define SB 1024
__global__ void k_scan1() {
    __shared__ int sh[SB];
    int g = blockIdx.x * SB + threadIdx.x;
    int v = (g < NN) ? g_deg[g] : 0;
    sh[threadIdx.x] = v;
    __syncthreads();
    for (int o = 1; o < SB; o <<= 1) {
        int t = (threadIdx.x >= o) ? sh[threadIdx.x - o] : 0;
        __syncthreads();
        sh[threadIdx.x] += t;
        __syncthreads();
    }
    if (g < NN) g_off[g] = sh[threadIdx.x] - v;   // exclusive
    if (threadIdx.x == SB - 1) g_bsum[blockIdx.x] = sh[SB - 1];
}
__global__ void k_scan2(int nb) {
    if (threadIdx.x == 0) {
        int acc = 0;
        for (int i = 0; i < nb; i++) { int t = g_bsum[i]; g_bsum[i] = acc; acc += t; }
    }
}
__global__ void k_scan3() {
    int g = blockIdx.x * SB + threadIdx.x;
    if (g < NN) g_off[g] += g_bsum[blockIdx.x];
    if (g == 0) g_off[NN] = ET;
}

__global__ void k_scatter(const void* ei) {
    int e = blockIdx.x * blockDim.x + threadIdx.x;
    if (e >= ET) return;
    int f = g_i64flag;
    int s, d;
    if (e < EE) { s = edge_at(ei, f, e); d = edge_at(ei, f, (long long)EE + e); }
    else        { s = d = e - EE; }
    int p = g_off[d] + atomicAdd(&g_cur[d], 1);
    g_csr[p] = s;
}

// ---------------- SGEMM: C[M,NC] = A[M,K] * W[K,NC] ----------------
// BM=128 BN=64 BK=16, 256 threads, 8x4 per thread
__global__ __launch_bounds__(256) void k_sgemm(const float* __restrict__ A,
                                               const float* __restrict__ W,
                                               float* __restrict__ C,
                                               int M, int K, int NC) {
    const int BM = 128, BN = 64, BK = 16, TM = 8, TN = 4;
    __shared__ float As[BK][BM];
    __shared__ float Bs[BK][BN];
    int tid = threadIdx.x;
    int tx = tid % 16, ty = tid / 16;
    int bm = blockIdx.y * BM, bn = blockIdx.x * BN;
    float acc[TM][TN];
#pragma unroll
    for (int i = 0; i < TM; i++)
#pragma unroll
        for (int j = 0; j < TN; j++) acc[i][j] = 0.f;

    for (int k0 = 0; k0 < K; k0 += BK) {
        // A tile: 128x16 = 512 float4, 2 per thread, store transposed
#pragma unroll
        for (int l = 0; l < 2; l++) {
            int idx = tid + l * 256;
            int r = idx >> 2;
            int c4 = idx & 3;
            int gr = bm + r;
            float4 v = make_float4(0.f, 0.f, 0.f, 0.f);
            if (gr < M) v = *(const float4*)(A + (size_t)gr * K + k0 + c4 * 4);
            As[c4 * 4 + 0][r] = v.x;
            As[c4 * 4 + 1][r] = v.y;
            As[c4 * 4 + 2][r] = v.z;
            As[c4 * 4 + 3][r] = v.w;
        }
        // B tile: 16x64 = 256 float4, 1 per thread
        {
            int r = tid >> 4;
            int c4 = tid & 15;
            int gc = bn + c4 * 4;
            float4 v = make_float4(0.f, 0.f, 0.f, 0.f);
            if (gc + 3 < NC) {
                v = *(const float4*)(W + (size_t)(k0 + r) * NC + gc);
            } else {
                float t[4] = {0.f, 0.f, 0.f, 0.f};
                for (int j = 0; j < 4; j++)
                    if (gc + j < NC) t[j] = W[(size_t)(k0 + r) * NC + gc + j];
                v = make_float4(t[0], t[1], t[2], t[3]);
            }
            *(float4*)&Bs[r][c4 * 4] = v;
        }
        __syncthreads();
#pragma unroll
        for (int k = 0; k < BK; k++) {
            float ra[TM], rb[TN];
            float4 a0 = *(const float4*)&As[k][ty * TM];
            float4 a1 = *(const float4*)&As[k][ty * TM + 4];
            ra[0] = a0.x; ra[1] = a0.y; ra[2] = a0.z; ra[3] = a0.w;
            ra[4] = a1.x; ra[5] = a1.y; ra[6] = a1.z; ra[7] = a1.w;
            float4 b0 = *(const float4*)&Bs[k][tx * TN];
            rb[0] = b0.x; rb[1] = b0.y; rb[2] = b0.z; rb[3] = b0.w;
#pragma unroll
            for (int i = 0; i < TM; i++)
#pragma unroll
                for (int j = 0; j < TN; j++) acc[i][j] += ra[i] * rb[j];
        }
        __syncthreads();
    }
#pragma unroll
    for (int i = 0; i < TM; i++) {
        int gr = bm + ty * TM + i;
        if (gr >= M) continue;
        int gc = bn + tx * TN;
        float* crow = C + (size_t)gr * NC + gc;
        if (gc + 3 < NC) {
            *(float4*)crow = make_float4(acc[i][0], acc[i][1], acc[i][2], acc[i][3]);
        } else {
            for (int j = 0; j < 4; j++)
                if (gc + j < NC) crow[j] = acc[i][j];
        }
    }
}

// ---------------- per-node attention projections ----------------
__global__ void k_proj256(const float* __restrict__ h,
                          const float* __restrict__ asv, const float* __restrict__ adv,
                          float* __restrict__ als, float* __restrict__ ald) {
    int gw = (blockIdx.x * blockDim.x + threadIdx.x) >> 5;
    if (gw >= NN) return;
    int lane = threadIdx.x & 31;
    const float* hr = h + (size_t)gw * HC + lane * 8;
    float4 p = *(const float4*)hr;
    float4 q = *(const float4*)(hr + 4);
    float4 s1 = *(const float4*)(asv + lane * 8);
    float4 s2 = *(const float4*)(asv + lane * 8 + 4);
    float4 d1 = *(const float4*)(adv + lane * 8);
    float4 d2 = *(const float4*)(adv + lane * 8 + 4);
    float ps = p.x * s1.x + p.y * s1.y + p.z * s1.z + p.w * s1.w +
               q.x * s2.x + q.y * s2.y + q.z * s2.z + q.w * s2.w;
    float pd = p.x * d1.x + p.y * d1.y + p.z * d1.z + p.w * d1.w +
               q.x * d2.x + q.y * d2.y + q.z * d2.z + q.w * d2.w;
#pragma unroll
    for (int o = 4; o >= 1; o >>= 1) {
        ps += __shfl_xor_sync(0xffffffffu, ps, o);
        pd += __shfl_xor_sync(0xffffffffu, pd, o);
    }
    if ((lane & 7) == 0) {
        int hh = lane >> 3;
        als[gw * 4 + hh] = ps;
        ald[gw * 4 + hh] = pd;
    }
}

__global__ void k_proj40(const float* __restrict__ h,
                         const float* __restrict__ asv, const float* __restrict__ adv,
                         float* __restrict__ als, float* __restrict__ ald) {
    int gw = (blockIdx.x * blockDim.x + threadIdx.x) >> 5;
    if (gw >= NN) return;
    int lane = threadIdx.x & 31;
    const float* hr = h + (size_t)gw * OUTC;
    float v0 = hr[lane];
    float v1 = (lane < 8) ? hr[32 + lane] : 0.f;
    float ps = v0 * asv[lane] + ((lane < 8) ? v1 * asv[32 + lane] : 0.f);
    float pd = v0 * adv[lane] + ((lane < 8) ? v1 * adv[32 + lane] : 0.f);
#pragma unroll
    for (int o = 16; o >= 1; o >>= 1) {
        ps += __shfl_xor_sync(0xffffffffu, ps, o);
        pd += __shfl_xor_sync(0xffffffffu, pd, o);
    }
    if (lane == 0) { als[gw] = ps; ald[gw] = pd; }
}

// ---------------- per-dst segment softmax (stores exp weights) ----------------
template <int H>
__global__ void k_attn(const float* __restrict__ als, const float* __restrict__ ald,
                       float* __restrict__ attn, float* __restrict__ rden) {
    int d = blockIdx.x * blockDim.x + threadIdx.x;
    if (d >= NN) return;
    int s0 = g_off[d], s1 = g_off[d + 1];
    float aldd[H], m[H];
#pragma unroll
    for (int h = 0; h < H; h++) { aldd[h] = ald[d * H + h]; m[h] = -1e30f; }
    for (int i = s0; i < s1; i++) {
        int s = g_csr[i];
#pragma unroll
        for (int h = 0; h < H; h++) {
            float a = als[s * H + h] + aldd[h];
            a = (a > 0.f) ? a : NEG * a;
            attn[(size_t)i * H + h] = a;
            m[h] = fmaxf(m[h], a);
        }
    }
    float den[H];
#pragma unroll
    for (int h = 0; h < H; h++) den[h] = 0.f;
    for (int i = s0; i < s1; i++) {
#pragma unroll
        for (int h = 0; h < H; h++) {
            float w = __expf(attn[(size_t)i * H + h] - m[h]);
            attn[(size_t)i * H + h] = w;
            den[h] += w;
        }
    }
#pragma unroll
    for (int h = 0; h < H; h++) rden[d * H + h] = 1.f / den[h];
}

// ---------------- aggregation gather: warp per dst ----------------
__global__ void k_gather256(const float* __restrict__ h, const float* __restrict__ bias,
                            const float* __restrict__ attn, const float* __restrict__ rden,
                            float* __restrict__ out, int doRelu) {
    int w = (blockIdx.x * blockDim.x + threadIdx.x) >> 5;
    if (w >= NN) return;
    int lane = threadIdx.x & 31;
    int head = lane >> 3;
    int s0 = g_off[w], s1 = g_off[w + 1];
    float acc[8] = {0.f, 0.f, 0.f, 0.f, 0.f, 0.f, 0.f, 0.f};
    for (int i = s0; i < s1; i++) {
        int s = g_csr[i];
        float wt = attn[(size_t)i * 4 + head];
        const float* hr = h + (size_t)s * HC + lane * 8;
        float4 p = *(const float4*)hr;
        float4 q = *(const float4*)(hr + 4);
        acc[0] += wt * p.x; acc[1] += wt * p.y; acc[2] += wt * p.z; acc[3] += wt * p.w;
        acc[4] += wt * q.x; acc[5] += wt * q.y; acc[6] += wt * q.z; acc[7] += wt * q.w;
    }
    float rd = rden[w * 4 + head];
    float4 b0 = *(const float4*)(bias + lane * 8);
    float4 b1 = *(const float4*)(bias + lane * 8 + 4);
    float v[8];
    v[0] = acc[0] * rd + b0.x; v[1] = acc[1] * rd + b0.y;
    v[2] = acc[2] * rd + b0.z; v[3] = acc[3] * rd + b0.w;
    v[4] = acc[4] * rd + b1.x; v[5] = acc[5] * rd + b1.y;
    v[6] = acc[6] * rd + b1.z; v[7] = acc[7] * rd + b1.w;
    if (doRelu) {
#pragma unroll
        for (int k = 0; k < 8; k++) v[k] = fmaxf(v[k], 0.f);
    }
    float* o = out + (size_t)w * HC + lane * 8;
    *(float4*)o = make_float4(v[0], v[1], v[2], v[3]);
    *(float4*)(o + 4) = make_float4(v[4], v[5], v[6], v[7]);
}

// layer 3: gather + bias + log_softmax fused
__global__ void k_gather40(const float* __restrict__ h, const float* __restrict__ bias,
                           const float* __restrict__ attn, const float* __restrict__ rden,
                           float* __restrict__ out) {
    int w = (blockIdx.x * blockDim.x + threadIdx.x) >> 5;
    if (w >= NN) return;
    int lane = threadIdx.x & 31;
    int s0 = g_off[w], s1 = g_off[w + 1];
    float a0 = 0.f, a1 = 0.f;
    for (int i = s0; i < s1; i++) {
        int s = g_csr[i];
        float wt = attn[i];
        const float* hr = h + (size_t)s * OUTC;
        a0 += wt * hr[lane];
        if (lane < 8) a1 += wt * hr[32 + lane];
    }
    float rd = rden[w];
    float v0 = a0 * rd + bias[lane];
    float v1 = (lane < 8) ? (a1 * rd + bias[32 + lane]) : -1e30f;
    float mx = fmaxf(v0, v1);
#pragma unroll
    for (int o = 16; o >= 1; o >>= 1) mx = fmaxf(mx, __shfl_xor_sync(0xffffffffu, mx, o));
    float se = __expf(v0 - mx) + ((lane < 8) ? __expf(v1 - mx) : 0.f);
#pragma unroll
    for (int o = 16; o >= 1; o >>= 1) se += __shfl_xor_sync(0xffffffffu, se, o);
    float lse = mx + __logf(se);
    float* orow = out + (size_t)w * OUTC;
    orow[lane] = v0 - lse;
    if (lane < 8) orow[32 + lane] = v1 - lse;
}

// ---------------- launch ----------------
extern "C" void kernel_launch(void* const* d_in, const int* in_sizes, int n_in,
                              void* d_out, int out_size) {
    const float* x   = (const float*)d_in[0];
    const void*  ei  = d_in[1];
    const float* W1  = (const float*)d_in[2];
    const float* as1 = (const float*)d_in[3];
    const float* ad1 = (const float*)d_in[4];
    const float* b1  = (const float*)d_in[5];
    const float* W2  = (const float*)d_in[6];
    const float* as2 = (const float*)d_in[7];
    const float* ad2 = (const float*)d_in[8];
    const float* b2  = (const float*)d_in[9];
    const float* W3  = (const float*)d_in[10];
    const float* as3 = (const float*)d_in[11];
    const float* ad3 = (const float*)d_in[12];
    const float* b3  = (const float*)d_in[13];
    float* out = (float*)d_out;

    float *bufH, *bufA, *als, *ald, *attn, *rden;
    cudaGetSymbolAddress((void**)&bufH, g_bufH);
    cudaGetSymbolAddress((void**)&bufA, g_bufA);
    cudaGetSymbolAddress((void**)&als,  g_als);
    cudaGetSymbolAddress((void**)&ald,  g_ald);
    cudaGetSymbolAddress((void**)&attn, g_attn);
    cudaGetSymbolAddress((void**)&rden, g_rden);

    const int TB = 256;
    int nodeBlocks = (NN + TB - 1) / TB;          // thread-per-node kernels
    int warpBlocks = (NN * 32 + TB - 1) / TB;     // warp-per-node kernels
    int edgeBlocks = (ET + TB - 1) / TB;
    int scanBlocks = (NN + SB - 1) / SB;          // 49

    // ---- CSR build ----
    k_detect<<<1, 256>>>((const int*)ei);
    k_zero<<<nodeBlocks, TB>>>();
    k_hist<<<edgeBlocks, TB>>>(ei);
    k_scan1<<<scanBlocks, SB>>>();
    k_scan2<<<1, 32>>>(scanBlocks);
    k_scan3<<<scanBlocks, SB>>>();
    k_scatter<<<edgeBlocks, TB>>>(ei);

    dim3 g1((HC + 63) / 64, (NN + 127) / 128);
    dim3 g3((OUTC + 63) / 64, (NN + 127) / 128);

    // ---- Layer 1 ----
    k_sgemm<<<g1, 256>>>(x, W1, bufH, NN, INC, HC);
    k_proj256<<<warpBlocks, TB>>>(bufH, as1, ad1, als, ald);
    k_attn<4><<<nodeBlocks, TB>>>(als, ald, attn, rden);
    k_gather256<<<warpBlocks, TB>>>(bufH, b1, attn, rden, bufA, 1);

    // ---- Layer 2 ----
    k_sgemm<<<g1, 256>>>(bufA, W2, bufH, NN, HC, HC);
    k_proj256<<<warpBlocks, TB>>>(bufH, as2, ad2, als, ald);
    k_attn<4><<<nodeBlocks, TB>>>(als, ald, attn, rden);
    k_gather256<<<warpBlocks, TB>>>(bufH, b2, attn, rden, bufA, 1);

    // ---- Layer 3 ----
    k_sgemm<<<g3, 256>>>(bufA, W3, bufH, NN, HC, OUTC);
    k_proj40<<<warpBlocks, TB>>>(bufH, as3, ad3, als, ald);
    k_attn<1><<<nodeBlocks, TB>>>(als, ald, attn, rden);
    k_gather40<<<warpBlocks, TB>>>(bufH, b3, attn, rden, out);
}

// round 2
// speedup vs baseline: 1.2809x; 1.2809x over previous
#include <cuda_runtime.h>
#include <cuda_bf16.h>
#include <math.h>
#include <stdint.h>

#define NN   50000
#define EE   800000
#define ET   (EE + NN)    // edges + self loops = 850000
#define INC  128
#define HC   256          // HEADS*HID
#define OUTC 40
#define NEG  0.2f

// ---------------- device scratch (no allocations allowed) ----------------
__device__ float g_bufH[(size_t)NN * HC];   // linear output of current layer
__device__ float g_bufA[(size_t)NN * HC];   // aggregated output / next input
__device__ float g_als[(size_t)NN * 4];
__device__ float g_ald[(size_t)NN * 4];
__device__ float g_attn[(size_t)ET * 4];    // per-edge attention scratch
__device__ float g_rden[(size_t)NN * 4];
__device__ int   g_off[NN + 1];
__device__ int   g_cur[NN];
__device__ int   g_deg[NN];
__device__ int   g_csr[ET];
__device__ int   g_bsum[64];
__device__ int   g_i64flag;

// ---------------- edge dtype detection (int64 vs int32) -------------------
__global__ void k_detect(const int* ei32) {
    __shared__ int any;
    if (threadIdx.x == 0) any = 0;
    __syncthreads();
    int bad = 0;
    for (int i = threadIdx.x; i < 4096; i += blockDim.x)
        if (ei32[2 * i + 1] != 0) bad = 1;
    if (bad) any = 1;
    __syncthreads();
    if (threadIdx.x == 0) g_i64flag = any ? 0 : 1;
}

__device__ __forceinline__ int edge_at(const void* ei, int f, long long pos) {
    return f ? (int)(((const long long*)ei)[pos]) : ((const int*)ei)[pos];
}

// ---------------- CSR build ----------------
__global__ void k_zero() {
    int i = blockIdx.x * blockDim.x + threadIdx.x;
    if (i < NN) { g_deg[i] = 0; g_cur[i] = 0; }
}

__global__ void k_hist(const void* ei) {
    int e = blockIdx.x * blockDim.x + threadIdx.x;
    if (e >= ET) return;
    int f = g_i64flag;
    int d = (e < EE) ? edge_at(ei, f, (long long)EE + e) : (e - EE);
    atomicAdd(&g_deg[d], 1);
}

#define SB 1024
__global__ void k_scan1() {
    __shared__ int sh[SB];
    int g = blockIdx.x * SB + threadIdx.x;
    int v = (g < NN) ? g_deg[g] : 0;
    sh[threadIdx.x] = v;
    __syncthreads();
    for (int o = 1; o < SB; o <<= 1) {
        int t = (threadIdx.x >= o) ? sh[threadIdx.x - o] : 0;
        __syncthreads();
        sh[threadIdx.x] += t;
        __syncthreads();
    }
    if (g < NN) g_off[g] = sh[threadIdx.x] - v;   // exclusive
    if (threadIdx.x == SB - 1) g_bsum[blockIdx.x] = sh[SB - 1];
}
__global__ void k_scan2(int nb) {
    if (threadIdx.x == 0) {
        int acc = 0;
        for (int i = 0; i < nb; i++) { int t = g_bsum[i]; g_bsum[i] = acc; acc += t; }
    }
}
__global__ void k_scan3() {
    int g = blockIdx.x * SB + threadIdx.x;
    if (g < NN) g_off[g] += g_bsum[blockIdx.x];
    if (g == 0) g_off[NN] = ET;
}

__global__ void k_scatter(const void* ei) {
    int e = blockIdx.x * blockDim.x + threadIdx.x;
    if (e >= ET) return;
    int f = g_i64flag;
    int s, d;
    if (e < EE) { s = edge_at(ei, f, e); d = edge_at(ei, f, (long long)EE + e); }
    else        { s = d = e - EE; }
    int p = g_off[d] + atomicAdd(&g_cur[d], 1);
    g_csr[p] = s;
}

// ---------------- tf32 tensor-core GEMM: C[M,NC] = A[M,K] * W[K,NC] ----------
// BM=128 BN=64 BK=32, 256 threads (8 warps: 4 along M x 2 along N),
// warp tile 32x32 via mma.sync.m16n8k8 tf32, ldmatrix-loaded fragments.

__device__ __forceinline__ uint32_t f2tf32(float f) {
    uint32_t u;
    asm("cvt.rna.tf32.f32 %0, %1;" : "=r"(u) : "f"(f));
    return u;
}

__device__ __forceinline__ void ldsm4(uint32_t* r, uint32_t addr) {
    asm volatile("ldmatrix.sync.aligned.m8n8.x4.shared.b16 {%0,%1,%2,%3}, [%4];"
                 : "=r"(r[0]), "=r"(r[1]), "=r"(r[2]), "=r"(r[3]) : "r"(addr));
}

__device__ __forceinline__ void mma_tf32(float4& d, const uint32_t* a, const uint32_t* b) {
    asm volatile(
        "mma.sync.aligned.m16n8k8.row.col.f32.tf32.tf32.f32 "
        "{%0,%1,%2,%3}, {%4,%5,%6,%7}, {%8,%9}, {%0,%1,%2,%3};\n"
        : "+f"(d.x), "+f"(d.y), "+f"(d.z), "+f"(d.w)
        : "r"(a[0]), "r"(a[1]), "r"(a[2]), "r"(a[3]), "r"(b[0]), "r"(b[1]));
}

#define LDK 36  // padded row stride in tf32 elems (144B = 16B-aligned, conflict-free)

__global__ __launch_bounds__(256) void k_mma(const float* __restrict__ A,
                                             const float* __restrict__ W,
                                             float* __restrict__ C,
                                             int M, int K, int NC) {
    __shared__ uint32_t As[128 * LDK];   // [row_m][k]
    __shared__ uint32_t Bs[64 * LDK];    // [col_n][k]  (W transposed)
    int tid = threadIdx.x;
    int lane = tid & 31, warp = tid >> 5;
    int wm = warp & 3, wn = warp >> 2;
    int bm = blockIdx.y * 128, bn = blockIdx.x * 64;

    float4 acc[2][4];
#pragma unroll
    for (int mt = 0; mt < 2; mt++)
#pragma unroll
        for (int nt = 0; nt < 4; nt++) acc[mt][nt] = make_float4(0.f, 0.f, 0.f, 0.f);

    float4 ra[4];   // staged A: 4 float4/thread  (128x32 tile)
    float4 rb[2];   // staged B: 2 float4/thread  (32x64 tile)

    // ---- stage k0=0 ----
#pragma unroll
    for (int i = 0; i < 4; i++) {
        int idx = i * 256 + tid;
        int row = idx >> 3, kc = idx & 7;
        int gr = bm + row;
        ra[i] = (gr < M) ? *(const float4*)(A + (size_t)gr * K + kc * 4)
                         : make_float4(0.f, 0.f, 0.f, 0.f);
    }
#pragma unroll
    for (int i = 0; i < 2; i++) {
        int idx = i * 256 + tid;
        int kr = idx >> 4, nc = idx & 15;
        int gc = bn + nc * 4;
        const float* wp = W + (size_t)kr * NC + gc;
        float4 v = make_float4(0.f, 0.f, 0.f, 0.f);
        if (gc + 3 < NC) v = *(const float4*)wp;
        else {
            if (gc + 0 < NC) v.x = wp[0];
            if (gc + 1 < NC) v.y = wp[1];
            if (gc + 2 < NC) v.z = wp[2];
            if (gc + 3 < NC) v.w = wp[3];
        }
        rb[i] = v;
    }

    uint32_t smA = (uint32_t)__cvta_generic_to_shared(As);
    uint32_t smB = (uint32_t)__cvta_generic_to_shared(Bs);
    int p = lane >> 3, r = lane & 7;

    for (int k0 = 0; k0 < K; k0 += 32) {
        // regs -> smem (convert to tf32 here, once per element)
#pragma unroll
        for (int i = 0; i < 4; i++) {
            int idx = i * 256 + tid;
            int row = idx >> 3, kc = idx & 7;
            uint32_t* ptr = &As[row * LDK + kc * 4];
            ptr[0] = f2tf32(ra[i].x); ptr[1] = f2tf32(ra[i].y);
            ptr[2] = f2tf32(ra[i].z); ptr[3] = f2tf32(ra[i].w);
        }
#pragma unroll
        for (int i = 0; i < 2; i++) {
            int idx = i * 256 + tid;
            int kr = idx >> 4, nc = idx & 15;
            Bs[(nc * 4 + 0) * LDK + kr] = f2tf32(rb[i].x);
            Bs[(nc * 4 + 1) * LDK + kr] = f2tf32(rb[i].y);
            Bs[(nc * 4 + 2) * LDK + kr] = f2tf32(rb[i].z);
            Bs[(nc * 4 + 3) * LDK + kr] = f2tf32(rb[i].w);
        }
        __syncthreads();

        // prefetch next tile into regs (LDG overlaps with mma below)
        int kn = k0 + 32;
        if (kn < K) {
#pragma unroll
            for (int i = 0; i < 4; i++) {
                int idx = i * 256 + tid;
                int row = idx >> 3, kc = idx & 7;
                int gr = bm + row;
                ra[i] = (gr < M) ? *(const float4*)(A + (size_t)gr * K + kn + kc * 4)
                                 : make_float4(0.f, 0.f, 0.f, 0.f);
            }
#pragma unroll
            for (int i = 0; i < 2; i++) {
                int idx = i * 256 + tid;
                int kr = idx >> 4, nc = idx & 15;
                int gc = bn + nc * 4;
                const float* wp = W + (size_t)(kn + kr) * NC + gc;
                float4 v = make_float4(0.f, 0.f, 0.f, 0.f);
                if (gc + 3 < NC) v = *(const float4*)wp;
                else {
                    if (gc + 0 < NC) v.x = wp[0];
                    if (gc + 1 < NC) v.y = wp[1];
                    if (gc + 2 < NC) v.z = wp[2];
                    if (gc + 3 < NC) v.w = wp[3];
                }
                rb[i] = v;
            }
        }

        // compute 4 k-steps of 8
#pragma unroll
        for (int ks = 0; ks < 4; ks++) {
            uint32_t afr[2][4], bfr[4][2];
#pragma unroll
            for (int mt = 0; mt < 2; mt++) {
                int row = wm * 32 + mt * 16 + (p & 1) * 8 + r;
                int col = ks * 8 + (p >> 1) * 4;
                ldsm4(afr[mt], smA + (uint32_t)(row * LDK + col) * 4u);
            }
#pragma unroll
            for (int nh = 0; nh < 2; nh++) {
                int rown = wn * 32 + nh * 16 + (p >> 1) * 8 + r;
                int col = ks * 8 + (p & 1) * 4;
                uint32_t tmp[4];
                ldsm4(tmp, smB + (uint32_t)(rown * LDK + col) * 4u);
                bfr[nh * 2 + 0][0] = tmp[0]; bfr[nh * 2 + 0][1] = tmp[1];
                bfr[nh * 2 + 1][0] = tmp[2]; bfr[nh * 2 + 1][1] = tmp[3];
            }
#pragma unroll
            for (int mt = 0; mt < 2; mt++)
#pragma unroll
                for (int nt = 0; nt < 4; nt++)
                    mma_tf32(acc[mt][nt], afr[mt], bfr[nt]);
        }
        __syncthreads();
    }

    // epilogue
    int gq = lane >> 2, tq = lane & 3;
#pragma unroll
    for (int mt = 0; mt < 2; mt++) {
#pragma unroll
        for (int nt = 0; nt < 4; nt++) {
            int col = bn + wn * 32 + nt * 8 + tq * 2;
            if (col >= NC) continue;
            float4 d = acc[mt][nt];
            int r0 = bm + wm * 32 + mt * 16 + gq;
            if (r0 < M) *(float2*)(C + (size_t)r0 * NC + col) = make_float2(d.x, d.y);
            int r1 = r0 + 8;
            if (r1 < M) *(float2*)(C + (size_t)r1 * NC + col) = make_float2(d.z, d.w);
        }
    }
}

// ---------------- per-node attention projections ----------------
__global__ void k_proj256(const float* __restrict__ h,
                          const float* __restrict__ asv, const float* __restrict__ adv,
                          float* __restrict__ als, float* __restrict__ ald) {
    int gw = (blockIdx.x * blockDim.x + threadIdx.x) >> 5;
    if (gw >= NN) return;
    int lane = threadIdx.x & 31;
    const float* hr = h + (size_t)gw * HC + lane * 8;
    float4 p = *(const float4*)hr;
    float4 q = *(const float4*)(hr + 4);
    float4 s1 = *(const float4*)(asv + lane * 8);
    float4 s2 = *(const float4*)(asv + lane * 8 + 4);
    float4 d1 = *(const float4*)(adv + lane * 8);
    float4 d2 = *(const float4*)(adv + lane * 8 + 4);
    float ps = p.x * s1.x + p.y * s1.y + p.z * s1.z + p.w * s1.w +
               q.x * s2.x + q.y * s2.y + q.z * s2.z + q.w * s2.w;
    float pd = p.x * d1.x + p.y * d1.y + p.z * d1.z + p.w * d1.w +
               q.x * d2.x + q.y * d2.y + q.z * d2.z + q.w * d2.w;
#pragma unroll
    for (int o = 4; o >= 1; o >>= 1) {
        ps += __shfl_xor_sync(0xffffffffu, ps, o);
        pd += __shfl_xor_sync(0xffffffffu, pd, o);
    }
    if ((lane & 7) == 0) {
        int hh = lane >> 3;
        als[gw * 4 + hh] = ps;
        ald[gw * 4 + hh] = pd;
    }
}

__global__ void k_proj40(const float* __restrict__ h,
                         const float* __restrict__ asv, const float* __restrict__ adv,
                         float* __restrict__ als, float* __restrict__ ald) {
    int gw = (blockIdx.x * blockDim.x + threadIdx.x) >> 5;
    if (gw >= NN) return;
    int lane = threadIdx.x & 31;
    const float* hr = h + (size_t)gw * OUTC;
    float v0 = hr[lane];
    float v1 = (lane < 8) ? hr[32 + lane] : 0.f;
    float ps = v0 * asv[lane] + ((lane < 8) ? v1 * asv[32 + lane] : 0.f);
    float pd = v0 * adv[lane] + ((lane < 8) ? v1 * adv[32 + lane] : 0.f);
#pragma unroll
    for (int o = 16; o >= 1; o >>= 1) {
        ps += __shfl_xor_sync(0xffffffffu, ps, o);
        pd += __shfl_xor_sync(0xffffffffu, pd, o);
    }
    if (lane == 0) { als[gw] = ps; ald[gw] = pd; }
}

// ---------------- per-dst segment softmax (stores exp weights) ----------------
template <int H>
__global__ void k_attn(const float* __restrict__ als, const float* __restrict__ ald,
                       float* __restrict__ attn, float* __restrict__ rden) {
    int d = blockIdx.x * blockDim.x + threadIdx.x;
    if (d >= NN) return;
    int s0 = g_off[d], s1 = g_off[d + 1];
    float aldd[H], m[H];
#pragma unroll
    for (int h = 0; h < H; h++) { aldd[h] = ald[d * H + h]; m[h] = -1e30f; }
    for (int i = s0; i < s1; i++) {
        int s = g_csr[i];
#pragma unroll
        for (int h = 0; h < H; h++) {
            float a = als[s * H + h] + aldd[h];
            a = (a > 0.f) ? a : NEG * a;
            attn[(size_t)i * H + h] = a;
            m[h] = fmaxf(m[h], a);
        }
    }
    float den[H];
#pragma unroll
    for (int h = 0; h < H; h++) den[h] = 0.f;
    for (int i = s0; i < s1; i++) {
#pragma unroll
        for (int h = 0; h < H; h++) {
            float w = __expf(attn[(size_t)i * H + h] - m[h]);
            attn[(size_t)i * H + h] = w;
            den[h] += w;
        }
    }
#pragma unroll
    for (int h = 0; h < H; h++) rden[d * H + h] = 1.f / den[h];
}

// ---------------- aggregation gather: warp per dst ----------------
__global__ void k_gather256(const float* __restrict__ h, const float* __restrict__ bias,
                            const float* __restrict__ attn, const float* __restrict__ rden,
                            float* __restrict__ out, int doRelu) {
    int w = (blockIdx.x * blockDim.x + threadIdx.x) >> 5;
    if (w >= NN) return;
    int lane = threadIdx.x & 31;
    int head = lane >> 3;
    int s0 = g_off[w], s1 = g_off[w + 1];
    float acc[8] = {0.f, 0.f, 0.f, 0.f, 0.f, 0.f, 0.f, 0.f};
    for (int i = s0; i < s1; i++) {
        int s = g_csr[i];
        float wt = attn[(size_t)i * 4 + head];
        const float* hr = h + (size_t)s * HC + lane * 8;
        float4 p = *(const float4*)hr;
        float4 q = *(const float4*)(hr + 4);
        acc[0] += wt * p.x; acc[1] += wt * p.y; acc[2] += wt * p.z; acc[3] += wt * p.w;
        acc[4] += wt * q.x; acc[5] += wt * q.y; acc[6] += wt * q.z; acc[7] += wt * q.w;
    }
    float rd = rden[w * 4 + head];
    float4 b0 = *(const float4*)(bias + lane * 8);
    float4 b1 = *(const float4*)(bias + lane * 8 + 4);
    float v[8];
    v[0] = acc[0] * rd + b0.x; v[1] = acc[1] * rd + b0.y;
    v[2] = acc[2] * rd + b0.z; v[3] = acc[3] * rd + b0.w;
    v[4] = acc[4] * rd + b1.x; v[5] = acc[5] * rd + b1.y;
    v[6] = acc[6] * rd + b1.z; v[7] = acc[7] * rd + b1.w;
    if (doRelu) {
#pragma unroll
        for (int k = 0; k < 8; k++) v[k] = fmaxf(v[k], 0.f);
    }
    float* o = out + (size_t)w * HC + lane * 8;
    *(float4*)o = make_float4(v[0], v[1], v[2], v[3]);
    *(float4*)(o + 4) = make_float4(v[4], v[5], v[6], v[7]);
}

// layer 3: gather + bias + log_softmax fused
__global__ void k_gather40(const float* __restrict__ h, const float* __restrict__ bias,
                           const float* __restrict__ attn, const float* __restrict__ rden,
                           float* __restrict__ out) {
    int w = (blockIdx.x * blockDim.x + threadIdx.x) >> 5;
    if (w >= NN) return;
    int lane = threadIdx.x & 31;
    int s0 = g_off[w], s1 = g_off[w + 1];
    float a0 = 0.f, a1 = 0.f;
    for (int i = s0; i < s1; i++) {
        int s = g_csr[i];
        float wt = attn[i];
        const float* hr = h + (size_t)s * OUTC;
        a0 += wt * hr[lane];
        if (lane < 8) a1 += wt * hr[32 + lane];
    }
    float rd = rden[w];
    float v0 = a0 * rd + bias[lane];
    float v1 = (lane < 8) ? (a1 * rd + bias[32 + lane]) : -1e30f;
    float mx = fmaxf(v0, v1);
#pragma unroll
    for (int o = 16; o >= 1; o >>= 1) mx = fmaxf(mx, __shfl_xor_sync(0xffffffffu, mx, o));
    float se = __expf(v0 - mx) + ((lane < 8) ? __expf(v1 - mx) : 0.f);
#pragma unroll
    for (int o = 16; o >= 1; o >>= 1) se += __shfl_xor_sync(0xffffffffu, se, o);
    float lse = mx + __logf(se);
    float* orow = out + (size_t)w * OUTC;
    orow[lane] = v0 - lse;
    if (lane < 8) orow[32 + lane] = v1 - lse;
}

// ---------------- launch ----------------
extern "C" void kernel_launch(void* const* d_in, const int* in_sizes, int n_in,
                              void* d_out, int out_size) {
    const float* x   = (const float*)d_in[0];
    const void*  ei  = d_in[1];
    const float* W1  = (const float*)d_in[2];
    const float* as1 = (const float*)d_in[3];
    const float* ad1 = (const float*)d_in[4];
    const float* b1  = (const float*)d_in[5];
    const float* W2  = (const float*)d_in[6];
    const float* as2 = (const float*)d_in[7];
    const float* ad2 = (const float*)d_in[8];
    const float* b2  = (const float*)d_in[9];
    const float* W3  = (const float*)d_in[10];
    const float* as3 = (const float*)d_in[11];
    const float* ad3 = (const float*)d_in[12];
    const float* b3  = (const float*)d_in[13];
    float* out = (float*)d_out;

    float *bufH, *bufA, *als, *ald, *attn, *rden;
    cudaGetSymbolAddress((void**)&bufH, g_bufH);
    cudaGetSymbolAddress((void**)&bufA, g_bufA);
    cudaGetSymbolAddress((void**)&als,  g_als);
    cudaGetSymbolAddress((void**)&ald,  g_ald);
    cudaGetSymbolAddress((void**)&attn, g_attn);
    cudaGetSymbolAddress((void**)&rden, g_rden);

    const int TB = 256;
    int nodeBlocks = (NN + TB - 1) / TB;          // thread-per-node kernels
    int warpBlocks = (NN * 32 + TB - 1) / TB;     // warp-per-node kernels
    int edgeBlocks = (ET + TB - 1) / TB;
    int scanBlocks = (NN + SB - 1) / SB;          // 49

    // ---- CSR build ----
    k_detect<<<1, 256>>>((const int*)ei);
    k_zero<<<nodeBlocks, TB>>>();
    k_hist<<<edgeBlocks, TB>>>(ei);
    k_scan1<<<scanBlocks, SB>>>();
    k_scan2<<<1, 32>>>(scanBlocks);
    k_scan3<<<scanBlocks, SB>>>();
    k_scatter<<<edgeBlocks, TB>>>(ei);

    dim3 g1((HC + 63) / 64, (NN + 127) / 128);    // (4, 391)
    dim3 g3(1, (NN + 127) / 128);                 // (1, 391)

    // ---- Layer 1 ----
    k_mma<<<g1, 256>>>(x, W1, bufH, NN, INC, HC);
    k_proj256<<<warpBlocks, TB>>>(bufH, as1, ad1, als, ald);
    k_attn<4><<<nodeBlocks, TB>>>(als, ald, attn, rden);
    k_gather256<<<warpBlocks, TB>>>(bufH, b1, attn, rden, bufA, 1);

    // ---- Layer 2 ----
    k_mma<<<g1, 256>>>(bufA, W2, bufH, NN, HC, HC);
    k_proj256<<<warpBlocks, TB>>>(bufH, as2, ad2, als, ald);
    k_attn<4><<<nodeBlocks, TB>>>(als, ald, attn, rden);
    k_gather256<<<warpBlocks, TB>>>(bufH, b2, attn, rden, bufA, 1);

    // ---- Layer 3 ----
    k_mma<<<g3, 256>>>(bufA, W3, bufH, NN, HC, OUTC);
    k_proj40<<<warpBlocks, TB>>>(bufH, as3, ad3, als, ald);
    k_attn<1><<<nodeBlocks, TB>>>(als, ald, attn, rden);
    k_gather40<<<warpBlocks, TB>>>(bufH, b3, attn, rden, out);
}

// round 3
// speedup vs baseline: 1.8686x; 1.4588x over previous
#include <cuda_runtime.h>
#include <cuda_bf16.h>
#include <math.h>
#include <stdint.h>

#define NN   50000
#define EE   800000
#define ET   (EE + NN)    // edges + self loops = 850000
#define INC  128
#define HC   256          // HEADS*HID
#define OUTC 40
#define NEG  0.2f

// ---------------- device scratch (no allocations allowed) ----------------
__device__ float          g_bufH[(size_t)NN * HC];   // fp32 h (layer 3 only)
__device__ float          g_bufA[(size_t)NN * HC];   // aggregated output / next input
__device__ __nv_bfloat16  g_bufHh[(size_t)NN * HC];  // bf16 h for gather (layers 1-2)
__device__ float g_als[(size_t)NN * 4];
__device__ float g_ald[(size_t)NN * 4];
__device__ float g_attn[(size_t)ET * 4];    // per-edge attention scratch
__device__ float g_rden[(size_t)NN * 4];
__device__ int   g_off[NN + 1];
__device__ int   g_cur[NN];
__device__ int   g_deg[NN];
__device__ int   g_csr[ET];
__device__ int   g_bsum[64];
__device__ int   g_i64flag;

// ---------------- edge dtype detection (int64 vs int32) -------------------
__global__ void k_detect(const int* ei32) {
    __shared__ int any;
    if (threadIdx.x == 0) any = 0;
    __syncthreads();
    int bad = 0;
    for (int i = threadIdx.x; i < 4096; i += blockDim.x)
        if (ei32[2 * i + 1] != 0) bad = 1;
    if (bad) any = 1;
    __syncthreads();
    if (threadIdx.x == 0) g_i64flag = any ? 0 : 1;
}

__device__ __forceinline__ int edge_at(const void* ei, int f, long long pos) {
    return f ? (int)(((const long long*)ei)[pos]) : ((const int*)ei)[pos];
}

// ---------------- CSR build ----------------
__global__ void k_zero() {
    int i = blockIdx.x * blockDim.x + threadIdx.x;
    if (i < NN) { g_deg[i] = 0; g_cur[i] = 0; }
}

__global__ void k_hist(const void* ei) {
    int e = blockIdx.x * blockDim.x + threadIdx.x;
    if (e >= ET) return;
    int f = g_i64flag;
    int d = (e < EE) ? edge_at(ei, f, (long long)EE + e) : (e - EE);
    atomicAdd(&g_deg[d], 1);
}

#define SB 1024
__global__ void k_scan1() {
    __shared__ int sh[SB];
    int g = blockIdx.x * SB + threadIdx.x;
    int v = (g < NN) ? g_deg[g] : 0;
    sh[threadIdx.x] = v;
    __syncthreads();
    for (int o = 1; o < SB; o <<= 1) {
        int t = (threadIdx.x >= o) ? sh[threadIdx.x - o] : 0;
        __syncthreads();
        sh[threadIdx.x] += t;
        __syncthreads();
    }
    if (g < NN) g_off[g] = sh[threadIdx.x] - v;   // exclusive
    if (threadIdx.x == SB - 1) g_bsum[blockIdx.x] = sh[SB - 1];
}
__global__ void k_scan2(int nb) {
    if (threadIdx.x == 0) {
        int acc = 0;
        for (int i = 0; i < nb; i++) { int t = g_bsum[i]; g_bsum[i] = acc; acc += t; }
    }
}
__global__ void k_scan3() {
    int g = blockIdx.x * SB + threadIdx.x;
    if (g < NN) g_off[g] += g_bsum[blockIdx.x];
    if (g == 0) g_off[NN] = ET;
}

__global__ void k_scatter(const void* ei) {
    int e = blockIdx.x * blockDim.x + threadIdx.x;
    if (e >= ET) return;
    int f = g_i64flag;
    int s, d;
    if (e < EE) { s = edge_at(ei, f, e); d = edge_at(ei, f, (long long)EE + e); }
    else        { s = d = e - EE; }
    int p = g_off[d] + atomicAdd(&g_cur[d], 1);
    g_csr[p] = s;
}

// ---------------- tf32 MMA helpers ----------------
__device__ __forceinline__ uint32_t f2tf32(float f) {
    uint32_t u;
    asm("cvt.rna.tf32.f32 %0, %1;" : "=r"(u) : "f"(f));
    return u;
}

__device__ __forceinline__ void ldsm4(uint32_t* r, uint32_t addr) {
    asm volatile("ldmatrix.sync.aligned.m8n8.x4.shared.b16 {%0,%1,%2,%3}, [%4];"
                 : "=r"(r[0]), "=r"(r[1]), "=r"(r[2]), "=r"(r[3]) : "r"(addr));
}

__device__ __forceinline__ void mma_tf32(float4& d, const uint32_t* a, const uint32_t* b) {
    asm volatile(
        "mma.sync.aligned.m16n8k8.row.col.f32.tf32.tf32.f32 "
        "{%0,%1,%2,%3}, {%4,%5,%6,%7}, {%8,%9}, {%0,%1,%2,%3};\n"
        : "+f"(d.x), "+f"(d.y), "+f"(d.z), "+f"(d.w)
        : "r"(a[0]), "r"(a[1]), "r"(a[2]), "r"(a[3]), "r"(b[0]), "r"(b[1]));
}

#define LDK 36  // padded row stride in tf32 elems

// ============ layer-1/2 GEMM: bf16 C + fused attention projections =========
// BM=128 BN=64 BK=32, 256 threads (8 warps: wm in [0,4) along M, wn in [0,2) along N)
// NC = 256 compile-time; each 64-col x-block == one head.
__global__ __launch_bounds__(256) void k_mma256(const float* __restrict__ A,
                                                const float* __restrict__ W,
                                                __nv_bfloat16* __restrict__ Cb,
                                                const float* __restrict__ asv,
                                                const float* __restrict__ adv,
                                                float* __restrict__ als,
                                                float* __restrict__ ald,
                                                int M, int K) {
    __shared__ uint32_t As[128 * LDK];
    __shared__ uint32_t Bs[64 * LDK];
    __shared__ float sAls[128][2];
    __shared__ float sAld[128][2];
    int tid = threadIdx.x;
    int lane = tid & 31, warp = tid >> 5;
    int wm = warp & 3, wn = warp >> 2;
    int bm = blockIdx.y * 128, bn = blockIdx.x * 64;
    int head = bn >> 6;

    float4 acc[2][4];
#pragma unroll
    for (int mt = 0; mt < 2; mt++)
#pragma unroll
        for (int nt = 0; nt < 4; nt++) acc[mt][nt] = make_float4(0.f, 0.f, 0.f, 0.f);

    float4 ra[4];
    float4 rb[2];

#pragma unroll
    for (int i = 0; i < 4; i++) {
        int idx = i * 256 + tid;
        int row = idx >> 3, kc = idx & 7;
        int gr = bm + row;
        ra[i] = (gr < M) ? *(const float4*)(A + (size_t)gr * K + kc * 4)
                         : make_float4(0.f, 0.f, 0.f, 0.f);
    }
#pragma unroll
    for (int i = 0; i < 2; i++) {
        int idx = i * 256 + tid;
        int kr = idx >> 4, nc = idx & 15;
        rb[i] = *(const float4*)(W + (size_t)kr * HC + bn + nc * 4);
    }

    uint32_t smA = (uint32_t)__cvta_generic_to_shared(As);
    uint32_t smB = (uint32_t)__cvta_generic_to_shared(Bs);
    int p = lane >> 3, r = lane & 7;

    for (int k0 = 0; k0 < K; k0 += 32) {
#pragma unroll
        for (int i = 0; i < 4; i++) {
            int idx = i * 256 + tid;
            int row = idx >> 3, kc = idx & 7;
            uint32_t* ptr = &As[row * LDK + kc * 4];
            ptr[0] = f2tf32(ra[i].x); ptr[1] = f2tf32(ra[i].y);
            ptr[2] = f2tf32(ra[i].z); ptr[3] = f2tf32(ra[i].w);
        }
#pragma unroll
        for (int i = 0; i < 2; i++) {
            int idx = i * 256 + tid;
            int kr = idx >> 4, nc = idx & 15;
            Bs[(nc * 4 + 0) * LDK + kr] = f2tf32(rb[i].x);
            Bs[(nc * 4 + 1) * LDK + kr] = f2tf32(rb[i].y);
            Bs[(nc * 4 + 2) * LDK + kr] = f2tf32(rb[i].z);
            Bs[(nc * 4 + 3) * LDK + kr] = f2tf32(rb[i].w);
        }
        __syncthreads();

        int kn = k0 + 32;
        if (kn < K) {
#pragma unroll
            for (int i = 0; i < 4; i++) {
                int idx = i * 256 + tid;
                int row = idx >> 3, kc = idx & 7;
                int gr = bm + row;
                ra[i] = (gr < M) ? *(const float4*)(A + (size_t)gr * K + kn + kc * 4)
                                 : make_float4(0.f, 0.f, 0.f, 0.f);
            }
#pragma unroll
            for (int i = 0; i < 2; i++) {
                int idx = i * 256 + tid;
                int kr = idx >> 4, nc = idx & 15;
                rb[i] = *(const float4*)(W + (size_t)(kn + kr) * HC + bn + nc * 4);
            }
        }

#pragma unroll
        for (int ks = 0; ks < 4; ks++) {
            uint32_t afr[2][4], bfr[4][2];
#pragma unroll
            for (int mt = 0; mt < 2; mt++) {
                int row = wm * 32 + mt * 16 + (p & 1) * 8 + r;
                int col = ks * 8 + (p >> 1) * 4;
                ldsm4(afr[mt], smA + (uint32_t)(row * LDK + col) * 4u);
            }
#pragma unroll
            for (int nh = 0; nh < 2; nh++) {
                int rown = wn * 32 + nh * 16 + (p >> 1) * 8 + r;
                int col = ks * 8 + (p & 1) * 4;
                uint32_t tmp[4];
                ldsm4(tmp, smB + (uint32_t)(rown * LDK + col) * 4u);
                bfr[nh * 2 + 0][0] = tmp[0]; bfr[nh * 2 + 0][1] = tmp[1];
                bfr[nh * 2 + 1][0] = tmp[2]; bfr[nh * 2 + 1][1] = tmp[3];
            }
#pragma unroll
            for (int mt = 0; mt < 2; mt++)
#pragma unroll
                for (int nt = 0; nt < 4; nt++)
                    mma_tf32(acc[mt][nt], afr[mt], bfr[nt]);
        }
        __syncthreads();
    }

    // ---- epilogue: bf16 store + fused attention projections ----
    int gq = lane >> 2, tq = lane & 3;
    const float* asvh = asv + head * 64;
    const float* advh = adv + head * 64;
#pragma unroll
    for (int mt = 0; mt < 2; mt++) {
        float va0 = 0.f, va1 = 0.f, vd0 = 0.f, vd1 = 0.f;
        int r0 = bm + wm * 32 + mt * 16 + gq;
        int r1 = r0 + 8;
#pragma unroll
        for (int nt = 0; nt < 4; nt++) {
            int cl = wn * 32 + nt * 8 + tq * 2;   // col within this head's 64
            float4 d = acc[mt][nt];
            // bf16 store
            if (r0 < M)
                *(__nv_bfloat162*)(Cb + (size_t)r0 * HC + bn + cl) =
                    __float22bfloat162_rn(make_float2(d.x, d.y));
            if (r1 < M)
                *(__nv_bfloat162*)(Cb + (size_t)r1 * HC + bn + cl) =
                    __float22bfloat162_rn(make_float2(d.z, d.w));
            float a0 = asvh[cl], a1 = asvh[cl + 1];
            float e0 = advh[cl], e1 = advh[cl + 1];
            va0 += d.x * a0 + d.y * a1;
            va1 += d.z * a0 + d.w * a1;
            vd0 += d.x * e0 + d.y * e1;
            vd1 += d.z * e0 + d.w * e1;
        }
#pragma unroll
        for (int o = 1; o <= 2; o <<= 1) {
            va0 += __shfl_xor_sync(0xffffffffu, va0, o);
            va1 += __shfl_xor_sync(0xffffffffu, va1, o);
            vd0 += __shfl_xor_sync(0xffffffffu, vd0, o);
            vd1 += __shfl_xor_sync(0xffffffffu, vd1, o);
        }
        if (tq == 0) {
            int lr = wm * 32 + mt * 16 + gq;
            sAls[lr][wn] = va0; sAls[lr + 8][wn] = va1;
            sAld[lr][wn] = vd0; sAld[lr + 8][wn] = vd1;
        }
    }
    __syncthreads();
    if (tid < 128) {
        int gr = bm + tid;
        if (gr < M) {
            als[gr * 4 + head] = sAls[tid][0] + sAls[tid][1];
            ald[gr * 4 + head] = sAld[tid][0] + sAld[tid][1];
        }
    }
}

// ============ generic fp32 GEMM (layer 3, NC=40) ============
__global__ __launch_bounds__(256) void k_mma(const float* __restrict__ A,
                                             const float* __restrict__ W,
                                             float* __restrict__ C,
                                             int M, int K, int NC) {
    __shared__ uint32_t As[128 * LDK];
    __shared__ uint32_t Bs[64 * LDK];
    int tid = threadIdx.x;
    int lane = tid & 31, warp = tid >> 5;
    int wm = warp & 3, wn = warp >> 2;
    int bm = blockIdx.y * 128, bn = blockIdx.x * 64;

    float4 acc[2][4];
#pragma unroll
    for (int mt = 0; mt < 2; mt++)
#pragma unroll
        for (int nt = 0; nt < 4; nt++) acc[mt][nt] = make_float4(0.f, 0.f, 0.f, 0.f);

    float4 ra[4];
    float4 rb[2];

#pragma unroll
    for (int i = 0; i < 4; i++) {
        int idx = i * 256 + tid;
        int row = idx >> 3, kc = idx & 7;
        int gr = bm + row;
        ra[i] = (gr < M) ? *(const float4*)(A + (size_t)gr * K + kc * 4)
                         : make_float4(0.f, 0.f, 0.f, 0.f);
    }
#pragma unroll
    for (int i = 0; i < 2; i++) {
        int idx = i * 256 + tid;
        int kr = idx >> 4, nc = idx & 15;
        int gc = bn + nc * 4;
        const float* wp = W + (size_t)kr * NC + gc;
        float4 v = make_float4(0.f, 0.f, 0.f, 0.f);
        if (gc + 3 < NC) v = *(const float4*)wp;
        else {
            if (gc + 0 < NC) v.x = wp[0];
            if (gc + 1 < NC) v.y = wp[1];
            if (gc + 2 < NC) v.z = wp[2];
            if (gc + 3 < NC) v.w = wp[3];
        }
        rb[i] = v;
    }

    uint32_t smA = (uint32_t)__cvta_generic_to_shared(As);
    uint32_t smB = (uint32_t)__cvta_generic_to_shared(Bs);
    int p = lane >> 3, r = lane & 7;

    for (int k0 = 0; k0 < K; k0 += 32) {
#pragma unroll
        for (int i = 0; i < 4; i++) {
            int idx = i * 256 + tid;
            int row = idx >> 3, kc = idx & 7;
            uint32_t* ptr = &As[row * LDK + kc * 4];
            ptr[0] = f2tf32(ra[i].x); ptr[1] = f2tf32(ra[i].y);
            ptr[2] = f2tf32(ra[i].z); ptr[3] = f2tf32(ra[i].w);
        }
#pragma unroll
        for (int i = 0; i < 2; i++) {
            int idx = i * 256 + tid;
            int kr = idx >> 4, nc = idx & 15;
            Bs[(nc * 4 + 0) * LDK + kr] = f2tf32(rb[i].x);
            Bs[(nc * 4 + 1) * LDK + kr] = f2tf32(rb[i].y);
            Bs[(nc * 4 + 2) * LDK + kr] = f2tf32(rb[i].z);
            Bs[(nc * 4 + 3) * LDK + kr] = f2tf32(rb[i].w);
        }
        __syncthreads();

        int kn = k0 + 32;
        if (kn < K) {
#pragma unroll
            for (int i = 0; i < 4; i++) {
                int idx = i * 256 + tid;
                int row = idx >> 3, kc = idx & 7;
                int gr = bm + row;
                ra[i] = (gr < M) ? *(const float4*)(A + (size_t)gr * K + kn + kc * 4)
                                 : make_float4(0.f, 0.f, 0.f, 0.f);
            }
#pragma unroll
            for (int i = 0; i < 2; i++) {
                int idx = i * 256 + tid;
                int kr = idx >> 4, nc = idx & 15;
                int gc = bn + nc * 4;
                const float* wp = W + (size_t)(kn + kr) * NC + gc;
                float4 v = make_float4(0.f, 0.f, 0.f, 0.f);
                if (gc + 3 < NC) v = *(const float4*)wp;
                else {
                    if (gc + 0 < NC) v.x = wp[0];
                    if (gc + 1 < NC) v.y = wp[1];
                    if (gc + 2 < NC) v.z = wp[2];
                    if (gc + 3 < NC) v.w = wp[3];
                }
                rb[i] = v;
            }
        }

#pragma unroll
        for (int ks = 0; ks < 4; ks++) {
            uint32_t afr[2][4], bfr[4][2];
#pragma unroll
            for (int mt = 0; mt < 2; mt++) {
                int row = wm * 32 + mt * 16 + (p & 1) * 8 + r;
                int col = ks * 8 + (p >> 1) * 4;
                ldsm4(afr[mt], smA + (uint32_t)(row * LDK + col) * 4u);
            }
#pragma unroll
            for (int nh = 0; nh < 2; nh++) {
                int rown = wn * 32 + nh * 16 + (p >> 1) * 8 + r;
                int col = ks * 8 + (p & 1) * 4;
                uint32_t tmp[4];
                ldsm4(tmp, smB + (uint32_t)(rown * LDK + col) * 4u);
                bfr[nh * 2 + 0][0] = tmp[0]; bfr[nh * 2 + 0][1] = tmp[1];
                bfr[nh * 2 + 1][0] = tmp[2]; bfr[nh * 2 + 1][1] = tmp[3];
            }
#pragma unroll
            for (int mt = 0; mt < 2; mt++)
#pragma unroll
                for (int nt = 0; nt < 4; nt++)
                    mma_tf32(acc[mt][nt], afr[mt], bfr[nt]);
        }
        __syncthreads();
    }

    int gq = lane >> 2, tq = lane & 3;
#pragma unroll
    for (int mt = 0; mt < 2; mt++) {
#pragma unroll
        for (int nt = 0; nt < 4; nt++) {
            int col = bn + wn * 32 + nt * 8 + tq * 2;
            if (col >= NC) continue;
            float4 d = acc[mt][nt];
            int r0 = bm + wm * 32 + mt * 16 + gq;
            if (r0 < M) *(float2*)(C + (size_t)r0 * NC + col) = make_float2(d.x, d.y);
            int r1 = r0 + 8;
            if (r1 < M) *(float2*)(C + (size_t)r1 * NC + col) = make_float2(d.z, d.w);
        }
    }
}

// ---------------- layer-3 attention projection ----------------
__global__ void k_proj40(const float* __restrict__ h,
                         const float* __restrict__ asv, const float* __restrict__ adv,
                         float* __restrict__ als, float* __restrict__ ald) {
    int gw = (blockIdx.x * blockDim.x + threadIdx.x) >> 5;
    if (gw >= NN) return;
    int lane = threadIdx.x & 31;
    const float* hr = h + (size_t)gw * OUTC;
    float v0 = hr[lane];
    float v1 = (lane < 8) ? hr[32 + lane] : 0.f;
    float ps = v0 * asv[lane] + ((lane < 8) ? v1 * asv[32 + lane] : 0.f);
    float pd = v0 * adv[lane] + ((lane < 8) ? v1 * adv[32 + lane] : 0.f);
#pragma unroll
    for (int o = 16; o >= 1; o >>= 1) {
        ps += __shfl_xor_sync(0xffffffffu, ps, o);
        pd += __shfl_xor_sync(0xffffffffu, pd, o);
    }
    if (lane == 0) { als[gw] = ps; ald[gw] = pd; }
}

// ---------------- warp-per-dst segment softmax (H=4) ----------------
__global__ void k_attnW4(const float4* __restrict__ als4, const float4* __restrict__ ald4,
                         float4* __restrict__ attn4, float4* __restrict__ rden4) {
    int w = (blockIdx.x * blockDim.x + threadIdx.x) >> 5;
    if (w >= NN) return;
    int lane = threadIdx.x & 31;
    int s0 = g_off[w], s1 = g_off[w + 1];
    float4 ad = ald4[w];
    float4 m = make_float4(-1e30f, -1e30f, -1e30f, -1e30f);
    for (int i = s0 + lane; i < s1; i += 32) {
        int s = g_csr[i];
        float4 a = als4[s];
        a.x += ad.x; a.y += ad.y; a.z += ad.z; a.w += ad.w;
        a.x = (a.x > 0.f) ? a.x : NEG * a.x;
        a.y = (a.y > 0.f) ? a.y : NEG * a.y;
        a.z = (a.z > 0.f) ? a.z : NEG * a.z;
        a.w = (a.w > 0.f) ? a.w : NEG * a.w;
        attn4[i] = a;
        m.x = fmaxf(m.x, a.x); m.y = fmaxf(m.y, a.y);
        m.z = fmaxf(m.z, a.z); m.w = fmaxf(m.w, a.w);
    }
#pragma unroll
    for (int o = 16; o >= 1; o >>= 1) {
        m.x = fmaxf(m.x, __shfl_xor_sync(0xffffffffu, m.x, o));
        m.y = fmaxf(m.y, __shfl_xor_sync(0xffffffffu, m.y, o));
        m.z = fmaxf(m.z, __shfl_xor_sync(0xffffffffu, m.z, o));
        m.w = fmaxf(m.w, __shfl_xor_sync(0xffffffffu, m.w, o));
    }
    float4 den = make_float4(0.f, 0.f, 0.f, 0.f);
    for (int i = s0 + lane; i < s1; i += 32) {
        float4 a = attn4[i];
        a.x = __expf(a.x - m.x); a.y = __expf(a.y - m.y);
        a.z = __expf(a.z - m.z); a.w = __expf(a.w - m.w);
        attn4[i] = a;
        den.x += a.x; den.y += a.y; den.z += a.z; den.w += a.w;
    }
#pragma unroll
    for (int o = 16; o >= 1; o >>= 1) {
        den.x += __shfl_xor_sync(0xffffffffu, den.x, o);
        den.y += __shfl_xor_sync(0xffffffffu, den.y, o);
        den.z += __shfl_xor_sync(0xffffffffu, den.z, o);
        den.w += __shfl_xor_sync(0xffffffffu, den.w, o);
    }
    if (lane == 0)
        rden4[w] = make_float4(1.f / den.x, 1.f / den.y, 1.f / den.z, 1.f / den.w);
}

// ---------------- warp-per-dst segment softmax (H=1, layer 3) ----------------
__global__ void k_attnW1(const float* __restrict__ als, const float* __restrict__ ald,
                         float* __restrict__ attn, float* __restrict__ rden) {
    int w = (blockIdx.x * blockDim.x + threadIdx.x) >> 5;
    if (w >= NN) return;
    int lane = threadIdx.x & 31;
    int s0 = g_off[w], s1 = g_off[w + 1];
    float ad = ald[w];
    float m = -1e30f;
    for (int i = s0 + lane; i < s1; i += 32) {
        int s = g_csr[i];
        float a = als[s] + ad;
        a = (a > 0.f) ? a : NEG * a;
        attn[i] = a;
        m = fmaxf(m, a);
    }
#pragma unroll
    for (int o = 16; o >= 1; o >>= 1) m = fmaxf(m, __shfl_xor_sync(0xffffffffu, m, o));
    float den = 0.f;
    for (int i = s0 + lane; i < s1; i += 32) {
        float a = __expf(attn[i] - m);
        attn[i] = a;
        den += a;
    }
#pragma unroll
    for (int o = 16; o >= 1; o >>= 1) den += __shfl_xor_sync(0xffffffffu, den, o);
    if (lane == 0) rden[w] = 1.f / den;
}

// ---------------- bf16 aggregation gather: warp per dst ----------------
__global__ void k_gather256(const __nv_bfloat16* __restrict__ hb,
                            const float* __restrict__ bias,
                            const float* __restrict__ attn, const float* __restrict__ rden,
                            float* __restrict__ out) {
    int w = (blockIdx.x * blockDim.x + threadIdx.x) >> 5;
    if (w >= NN) return;
    int lane = threadIdx.x & 31;
    int head = lane >> 3;
    int s0 = g_off[w], s1 = g_off[w + 1];
    float acc[8] = {0.f, 0.f, 0.f, 0.f, 0.f, 0.f, 0.f, 0.f};
    for (int i = s0; i < s1; i++) {
        int s = g_csr[i];
        float wt = attn[(size_t)i * 4 + head];
        const __nv_bfloat16* hr = hb + (size_t)s * HC + lane * 8;
        uint4 u = *(const uint4*)hr;
        float2 f0 = __bfloat1622float2(*(__nv_bfloat162*)&u.x);
        float2 f1 = __bfloat1622float2(*(__nv_bfloat162*)&u.y);
        float2 f2 = __bfloat1622float2(*(__nv_bfloat162*)&u.z);
        float2 f3 = __bfloat1622float2(*(__nv_bfloat162*)&u.w);
        acc[0] += wt * f0.x; acc[1] += wt * f0.y;
        acc[2] += wt * f1.x; acc[3] += wt * f1.y;
        acc[4] += wt * f2.x; acc[5] += wt * f2.y;
        acc[6] += wt * f3.x; acc[7] += wt * f3.y;
    }
    float rd = rden[w * 4 + head];
    float4 b0 = *(const float4*)(bias + lane * 8);
    float4 b1 = *(const float4*)(bias + lane * 8 + 4);
    float v[8];
    v[0] = acc[0] * rd + b0.x; v[1] = acc[1] * rd + b0.y;
    v[2] = acc[2] * rd + b0.z; v[3] = acc[3] * rd + b0.w;
    v[4] = acc[4] * rd + b1.x; v[5] = acc[5] * rd + b1.y;
    v[6] = acc[6] * rd + b1.z; v[7] = acc[7] * rd + b1.w;
#pragma unroll
    for (int k = 0; k < 8; k++) v[k] = fmaxf(v[k], 0.f);   // relu (layers 1-2 only)
    float* o = out + (size_t)w * HC + lane * 8;
    *(float4*)o = make_float4(v[0], v[1], v[2], v[3]);
    *(float4*)(o + 4) = make_float4(v[4], v[5], v[6], v[7]);
}

// layer 3: gather + bias + log_softmax fused (fp32 h)
__global__ void k_gather40(const float* __restrict__ h, const float* __restrict__ bias,
                           const float* __restrict__ attn, const float* __restrict__ rden,
                           float* __restrict__ out) {
    int w = (blockIdx.x * blockDim.x + threadIdx.x) >> 5;
    if (w >= NN) return;
    int lane = threadIdx.x & 31;
    int s0 = g_off[w], s1 = g_off[w + 1];
    float a0 = 0.f, a1 = 0.f;
    for (int i = s0; i < s1; i++) {
        int s = g_csr[i];
        float wt = attn[i];
        const float* hr = h + (size_t)s * OUTC;
        a0 += wt * hr[lane];
        if (lane < 8) a1 += wt * hr[32 + lane];
    }
    float rd = rden[w];
    float v0 = a0 * rd + bias[lane];
    float v1 = (lane < 8) ? (a1 * rd + bias[32 + lane]) : -1e30f;
    float mx = fmaxf(v0, v1);
#pragma unroll
    for (int o = 16; o >= 1; o >>= 1) mx = fmaxf(mx, __shfl_xor_sync(0xffffffffu, mx, o));
    float se = __expf(v0 - mx) + ((lane < 8) ? __expf(v1 - mx) : 0.f);
#pragma unroll
    for (int o = 16; o >= 1; o >>= 1) se += __shfl_xor_sync(0xffffffffu, se, o);
    float lse = mx + __logf(se);
    float* orow = out + (size_t)w * OUTC;
    orow[lane] = v0 - lse;
    if (lane < 8) orow[32 + lane] = v1 - lse;
}

// ---------------- launch ----------------
extern "C" void kernel_launch(void* const* d_in, const int* in_sizes, int n_in,
                              void* d_out, int out_size) {
    const float* x   = (const float*)d_in[0];
    const void*  ei  = d_in[1];
    const float* W1  = (const float*)d_in[2];
    const float* as1 = (const float*)d_in[3];
    const float* ad1 = (const float*)d_in[4];
    const float* b1  = (const float*)d_in[5];
    const float* W2  = (const float*)d_in[6];
    const float* as2 = (const float*)d_in[7];
    const float* ad2 = (const float*)d_in[8];
    const float* b2  = (const float*)d_in[9];
    const float* W3  = (const float*)d_in[10];
    const float* as3 = (const float*)d_in[11];
    const float* ad3 = (const float*)d_in[12];
    const float* b3  = (const float*)d_in[13];
    float* out = (float*)d_out;

    float *bufH, *bufA, *als, *ald, *attn, *rden;
    __nv_bfloat16* bufHh;
    cudaGetSymbolAddress((void**)&bufH,  g_bufH);
    cudaGetSymbolAddress((void**)&bufA,  g_bufA);
    cudaGetSymbolAddress((void**)&bufHh, g_bufHh);
    cudaGetSymbolAddress((void**)&als,   g_als);
    cudaGetSymbolAddress((void**)&ald,   g_ald);
    cudaGetSymbolAddress((void**)&attn,  g_attn);
    cudaGetSymbolAddress((void**)&rden,  g_rden);

    const int TB = 256;
    int nodeBlocks = (NN + TB - 1) / TB;
    int warpBlocks = (NN * 32 + TB - 1) / TB;
    int edgeBlocks = (ET + TB - 1) / TB;
    int scanBlocks = (NN + SB - 1) / SB;

    // ---- CSR build ----
    k_detect<<<1, 256>>>((const int*)ei);
    k_zero<<<nodeBlocks, TB>>>();
    k_hist<<<edgeBlocks, TB>>>(ei);
    k_scan1<<<scanBlocks, SB>>>();
    k_scan2<<<1, 32>>>(scanBlocks);
    k_scan3<<<scanBlocks, SB>>>();
    k_scatter<<<edgeBlocks, TB>>>(ei);

    dim3 g1(4, (NN + 127) / 128);     // (4, 391)
    dim3 g3(1, (NN + 127) / 128);     // (1, 391)

    // ---- Layer 1 ----
    k_mma256<<<g1, 256>>>(x, W1, bufHh, as1, ad1, als, ald, NN, INC);
    k_attnW4<<<warpBlocks, TB>>>((const float4*)als, (const float4*)ald,
                                 (float4*)attn, (float4*)rden);
    k_gather256<<<warpBlocks, TB>>>(bufHh, b1, attn, rden, bufA);

    // ---- Layer 2 ----
    k_mma256<<<g1, 256>>>(bufA, W2, bufHh, as2, ad2, als, ald, NN, HC);
    k_attnW4<<<warpBlocks, TB>>>((const float4*)als, (const float4*)ald,
                                 (float4*)attn, (float4*)rden);
    k_gather256<<<warpBlocks, TB>>>(bufHh, b2, attn, rden, bufA);

    // ---- Layer 3 ----
    k_mma<<<g3, 256>>>(bufA, W3, bufH, NN, HC, OUTC);
    k_proj40<<<warpBlocks, TB>>>(bufH, as3, ad3, als, ald);
    k_attnW1<<<warpBlocks, TB>>>(als, ald, attn, rden);
    k_gather40<<<warpBlocks, TB>>>(bufH, b3, attn, rden, out);
}

// round 4
// speedup vs baseline: 2.1096x; 1.1290x over previous
#include <cuda_runtime.h>
#include <cuda_bf16.h>
#include <math.h>
#include <stdint.h>

#define NN   50000
#define EE   800000
#define ET   (EE + NN)    // edges + self loops = 850000
#define INC  128
#define HC   256          // HEADS*HID
#define OUTC 40
#define NEG  0.2f

// ---------------- device scratch (no allocations allowed) ----------------
__device__ __nv_bfloat16  g_xh[(size_t)NN * INC];    // bf16 copy of x
__device__ __nv_bfloat16  g_bufHh[(size_t)NN * HC];  // bf16 h (GEMM out, layers 1-2)
__device__ __nv_bfloat16  g_bufAh[(size_t)NN * HC];  // bf16 aggregated (next GEMM in)
__device__ float          g_bufH3[(size_t)NN * OUTC];// fp32 h (layer 3)
__device__ float g_als[(size_t)NN * 4];
__device__ float g_ald[(size_t)NN * 4];
__device__ float g_attn[(size_t)ET * 4];    // per-edge attention scratch
__device__ float g_rden[(size_t)NN * 4];
__device__ int   g_off[NN + 1];
__device__ int   g_cur[NN];
__device__ int   g_deg[NN];
__device__ int   g_csr[ET];
__device__ int   g_bsum[64];
__device__ int   g_i64flag;

// ---------------- edge dtype detection (int64 vs int32) -------------------
__global__ void k_detect(const int* ei32) {
    __shared__ int any;
    if (threadIdx.x == 0) any = 0;
    __syncthreads();
    int bad = 0;
    for (int i = threadIdx.x; i < 4096; i += blockDim.x)
        if (ei32[2 * i + 1] != 0) bad = 1;
    if (bad) any = 1;
    __syncthreads();
    if (threadIdx.x == 0) g_i64flag = any ? 0 : 1;
}

__device__ __forceinline__ int edge_at(const void* ei, int f, long long pos) {
    return f ? (int)(((const long long*)ei)[pos]) : ((const int*)ei)[pos];
}

// ---------------- CSR build ----------------
__global__ void k_zero() {
    int i = blockIdx.x * blockDim.x + threadIdx.x;
    if (i < NN) { g_deg[i] = 0; g_cur[i] = 0; }
}

__global__ void k_hist(const void* ei) {
    int e = blockIdx.x * blockDim.x + threadIdx.x;
    if (e >= ET) return;
    int f = g_i64flag;
    int d = (e < EE) ? edge_at(ei, f, (long long)EE + e) : (e - EE);
    atomicAdd(&g_deg[d], 1);
}

#define SB 1024
__global__ void k_scan1() {
    __shared__ int sh[SB];
    int g = blockIdx.x * SB + threadIdx.x;
    int v = (g < NN) ? g_deg[g] : 0;
    sh[threadIdx.x] = v;
    __syncthreads();
    for (int o = 1; o < SB; o <<= 1) {
        int t = (threadIdx.x >= o) ? sh[threadIdx.x - o] : 0;
        __syncthreads();
        sh[threadIdx.x] += t;
        __syncthreads();
    }
    if (g < NN) g_off[g] = sh[threadIdx.x] - v;   // exclusive
    if (threadIdx.x == SB - 1) g_bsum[blockIdx.x] = sh[SB - 1];
}
__global__ void k_scan2(int nb) {
    if (threadIdx.x == 0) {
        int acc = 0;
        for (int i = 0; i < nb; i++) { int t = g_bsum[i]; g_bsum[i] = acc; acc += t; }
    }
}
__global__ void k_scan3() {
    int g = blockIdx.x * SB + threadIdx.x;
    if (g < NN) g_off[g] += g_bsum[blockIdx.x];
    if (g == 0) g_off[NN] = ET;
}

__global__ void k_scatter(const void* ei) {
    int e = blockIdx.x * blockDim.x + threadIdx.x;
    if (e >= ET) return;
    int f = g_i64flag;
    int s, d;
    if (e < EE) { s = edge_at(ei, f, e); d = edge_at(ei, f, (long long)EE + e); }
    else        { s = d = e - EE; }
    int p = g_off[d] + atomicAdd(&g_cur[d], 1);
    g_csr[p] = s;
}

// ---------------- x -> bf16 ----------------
__global__ void k_cvt(const float* __restrict__ x, __nv_bfloat16* __restrict__ xh, int n8) {
    int i = blockIdx.x * blockDim.x + threadIdx.x;
    if (i >= n8) return;
    const float4* p = (const float4*)(x + (size_t)i * 8);
    float4 a = p[0], b = p[1];
    uint4 u;
    *(__nv_bfloat162*)&u.x = __float22bfloat162_rn(make_float2(a.x, a.y));
    *(__nv_bfloat162*)&u.y = __float22bfloat162_rn(make_float2(a.z, a.w));
    *(__nv_bfloat162*)&u.z = __float22bfloat162_rn(make_float2(b.x, b.y));
    *(__nv_bfloat162*)&u.w = __float22bfloat162_rn(make_float2(b.z, b.w));
    *(uint4*)(xh + (size_t)i * 8) = u;
}

// ---------------- bf16 MMA helpers ----------------
__device__ __forceinline__ void ldsm4(uint32_t* r, uint32_t addr) {
    asm volatile("ldmatrix.sync.aligned.m8n8.x4.shared.b16 {%0,%1,%2,%3}, [%4];"
                 : "=r"(r[0]), "=r"(r[1]), "=r"(r[2]), "=r"(r[3]) : "r"(addr));
}

__device__ __forceinline__ void mma_bf16(float4& d, const uint32_t* a, const uint32_t* b) {
    asm volatile(
        "mma.sync.aligned.m16n8k16.row.col.f32.bf16.bf16.f32 "
        "{%0,%1,%2,%3}, {%4,%5,%6,%7}, {%8,%9}, {%0,%1,%2,%3};\n"
        : "+f"(d.x), "+f"(d.y), "+f"(d.z), "+f"(d.w)
        : "r"(a[0]), "r"(a[1]), "r"(a[2]), "r"(a[3]), "r"(b[0]), "r"(b[1]));
}

// C-store helpers (overloaded on output type)
__device__ __forceinline__ void store_c(__nv_bfloat16* C, size_t r, int stride, int col,
                                        float x, float y, int ncq) {
    *(__nv_bfloat162*)(C + r * stride + col) = __float22bfloat162_rn(make_float2(x, y));
}
__device__ __forceinline__ void store_c(float* C, size_t r, int stride, int col,
                                        float x, float y, int ncq) {
    if (col < ncq) *(float2*)(C + r * stride + col) = make_float2(x, y);
}

#define LDA 40  // padded smem row stride in bf16 elems (80B, 16B-aligned)

// ============ bf16 GEMM + fused attention projections =====================
// C[M,NCQ] = A[M,K](bf16) * W[K,NCQ](fp32, converted in staging)
// BM=128 BN=64 BK=32, 256 threads (8 warps: 4 x M, 2 x N), m16n8k16 bf16 MMA.
// Epilogue stores C and reduces als/ald = C . a_src / a_dst for this head
// (head = blockIdx.x; for NCQ<64 columns >= NCQ are masked).
template<int NCQ, int HSTR, typename CT>
__global__ __launch_bounds__(256) void k_gemmb(const __nv_bfloat16* __restrict__ A,
                                               const float* __restrict__ W,
                                               CT* __restrict__ C,
                                               const float* __restrict__ asv,
                                               const float* __restrict__ adv,
                                               float* __restrict__ als,
                                               float* __restrict__ ald,
                                               int M, int K) {
    __shared__ __nv_bfloat16 As[128 * LDA];
    __shared__ __nv_bfloat16 Bs[64 * LDA];
    __shared__ float sAls[128][2];
    __shared__ float sAld[128][2];
    int tid = threadIdx.x;
    int lane = tid & 31, warp = tid >> 5;
    int wm = warp & 3, wn = warp >> 2;
    int bm = blockIdx.y * 128, bn = blockIdx.x * 64;
    int head = blockIdx.x;

    float4 acc[2][4];
#pragma unroll
    for (int mt = 0; mt < 2; mt++)
#pragma unroll
        for (int nt = 0; nt < 4; nt++) acc[mt][nt] = make_float4(0.f, 0.f, 0.f, 0.f);

    uint4  ra[2];   // staged A: 2 x 8 bf16 per thread (128x32 tile)
    float4 rb[2];   // staged W: 2 x float4 per thread  (32x64 tile)

    // ---- stage k0 = 0 ----
#pragma unroll
    for (int i = 0; i < 2; i++) {
        int idx = i * 256 + tid;
        int row = idx >> 2, c8 = idx & 3;
        int gr = bm + row;
        ra[i] = (gr < M) ? *(const uint4*)(A + (size_t)gr * K + c8 * 8)
                         : make_uint4(0u, 0u, 0u, 0u);
    }
#pragma unroll
    for (int i = 0; i < 2; i++) {
        int idx = i * 256 + tid;
        int kr = idx >> 4, nc4 = idx & 15;
        int gc = bn + nc4 * 4;
        const float* wp = W + (size_t)kr * NCQ + gc;
        float4 v = make_float4(0.f, 0.f, 0.f, 0.f);
        if (NCQ >= 64 || gc + 3 < NCQ) {
            if (NCQ >= 64 || gc < NCQ) v = *(const float4*)wp;
        } else {
            if (gc + 0 < NCQ) v.x = wp[0];
            if (gc + 1 < NCQ) v.y = wp[1];
            if (gc + 2 < NCQ) v.z = wp[2];
            if (gc + 3 < NCQ) v.w = wp[3];
        }
        rb[i] = v;
    }

    uint32_t smA = (uint32_t)__cvta_generic_to_shared(As);
    uint32_t smB = (uint32_t)__cvta_generic_to_shared(Bs);

    for (int k0 = 0; k0 < K; k0 += 32) {
        // regs -> smem
#pragma unroll
        for (int i = 0; i < 2; i++) {
            int idx = i * 256 + tid;
            int row = idx >> 2, c8 = idx & 3;
            *(uint4*)(As + row * LDA + c8 * 8) = ra[i];
        }
#pragma unroll
        for (int i = 0; i < 2; i++) {
            int idx = i * 256 + tid;
            int kr = idx >> 4, nc4 = idx & 15;
            Bs[(nc4 * 4 + 0) * LDA + kr] = __float2bfloat16(rb[i].x);
            Bs[(nc4 * 4 + 1) * LDA + kr] = __float2bfloat16(rb[i].y);
            Bs[(nc4 * 4 + 2) * LDA + kr] = __float2bfloat16(rb[i].z);
            Bs[(nc4 * 4 + 3) * LDA + kr] = __float2bfloat16(rb[i].w);
        }
        __syncthreads();

        // prefetch next tile into regs
        int kn = k0 + 32;
        if (kn < K) {
#pragma unroll
            for (int i = 0; i < 2; i++) {
                int idx = i * 256 + tid;
                int row = idx >> 2, c8 = idx & 3;
                int gr = bm + row;
                ra[i] = (gr < M) ? *(const uint4*)(A + (size_t)gr * K + kn + c8 * 8)
                                 : make_uint4(0u, 0u, 0u, 0u);
            }
#pragma unroll
            for (int i = 0; i < 2; i++) {
                int idx = i * 256 + tid;
                int kr = idx >> 4, nc4 = idx & 15;
                int gc = bn + nc4 * 4;
                const float* wp = W + (size_t)(kn + kr) * NCQ + gc;
                float4 v = make_float4(0.f, 0.f, 0.f, 0.f);
                if (NCQ >= 64 || gc + 3 < NCQ) {
                    if (NCQ >= 64 || gc < NCQ) v = *(const float4*)wp;
                } else {
                    if (gc + 0 < NCQ) v.x = wp[0];
                    if (gc + 1 < NCQ) v.y = wp[1];
                    if (gc + 2 < NCQ) v.z = wp[2];
                    if (gc + 3 < NCQ) v.w = wp[3];
                }
                rb[i] = v;
            }
        }

        // 2 k16 steps
#pragma unroll
        for (int ks = 0; ks < 2; ks++) {
            int kk = ks * 16;
            uint32_t afr[2][4], bfr[4][2];
#pragma unroll
            for (int mt = 0; mt < 2; mt++) {
                int mrow = wm * 32 + mt * 16 + (lane & 15);
                int kc = kk + ((lane >> 4) << 3);
                ldsm4(afr[mt], smA + (uint32_t)(mrow * LDA + kc) * 2u);
            }
#pragma unroll
            for (int nh = 0; nh < 2; nh++) {
                int nrow = wn * 32 + nh * 16 + ((lane >> 4) << 3) + (lane & 7);
                int kc = kk + (((lane >> 3) & 1) << 3);
                uint32_t tmp[4];
                ldsm4(tmp, smB + (uint32_t)(nrow * LDA + kc) * 2u);
                bfr[nh * 2 + 0][0] = tmp[0]; bfr[nh * 2 + 0][1] = tmp[1];
                bfr[nh * 2 + 1][0] = tmp[2]; bfr[nh * 2 + 1][1] = tmp[3];
            }
#pragma unroll
            for (int mt = 0; mt < 2; mt++)
#pragma unroll
                for (int nt = 0; nt < 4; nt++)
                    mma_bf16(acc[mt][nt], afr[mt], bfr[nt]);
        }
        __syncthreads();
    }

    // ---- epilogue: C store + fused attention projections ----
    int gq = lane >> 2, tq = lane & 3;
    const float* asvh = asv + head * 64;
    const float* advh = adv + head * 64;
#pragma unroll
    for (int mt = 0; mt < 2; mt++) {
        float va0 = 0.f, va1 = 0.f, vd0 = 0.f, vd1 = 0.f;
        int r0 = bm + wm * 32 + mt * 16 + gq;
        int r1 = r0 + 8;
#pragma unroll
        for (int nt = 0; nt < 4; nt++) {
            int cl = wn * 32 + nt * 8 + tq * 2;   // col within this 64-block
            float4 d = acc[mt][nt];
            if (r0 < M) store_c(C, (size_t)r0, NCQ, bn + cl, d.x, d.y, NCQ);
            if (r1 < M) store_c(C, (size_t)r1, NCQ, bn + cl, d.z, d.w, NCQ);
            float a0 = (NCQ >= 64 || cl + 0 < NCQ) ? asvh[cl] : 0.f;
            float a1 = (NCQ >= 64 || cl + 1 < NCQ) ? asvh[cl + 1] : 0.f;
            float e0 = (NCQ >= 64 || cl + 0 < NCQ) ? advh[cl] : 0.f;
            float e1 = (NCQ >= 64 || cl + 1 < NCQ) ? advh[cl + 1] : 0.f;
            va0 += d.x * a0 + d.y * a1;
            va1 += d.z * a0 + d.w * a1;
            vd0 += d.x * e0 + d.y * e1;
            vd1 += d.z * e0 + d.w * e1;
        }
#pragma unroll
        for (int o = 1; o <= 2; o <<= 1) {
            va0 += __shfl_xor_sync(0xffffffffu, va0, o);
            va1 += __shfl_xor_sync(0xffffffffu, va1, o);
            vd0 += __shfl_xor_sync(0xffffffffu, vd0, o);
            vd1 += __shfl_xor_sync(0xffffffffu, vd1, o);
        }
        if (tq == 0) {
            int lr = wm * 32 + mt * 16 + gq;
            sAls[lr][wn] = va0; sAls[lr + 8][wn] = va1;
            sAld[lr][wn] = vd0; sAld[lr + 8][wn] = vd1;
        }
    }
    __syncthreads();
    if (tid < 128) {
        int gr = bm + tid;
        if (gr < M) {
            als[(size_t)gr * HSTR + head] = sAls[tid][0] + sAls[tid][1];
            ald[(size_t)gr * HSTR + head] = sAld[tid][0] + sAld[tid][1];
        }
    }
}

// ---------------- warp-per-dst segment softmax (H=4) ----------------
__global__ void k_attnW4(const float4* __restrict__ als4, const float4* __restrict__ ald4,
                         float4* __restrict__ attn4, float4* __restrict__ rden4) {
    int w = (blockIdx.x * blockDim.x + threadIdx.x) >> 5;
    if (w >= NN) return;
    int lane = threadIdx.x & 31;
    int s0 = g_off[w], s1 = g_off[w + 1];
    float4 ad = ald4[w];
    float4 m = make_float4(-1e30f, -1e30f, -1e30f, -1e30f);
    for (int i = s0 + lane; i < s1; i += 32) {
        int s = g_csr[i];
        float4 a = als4[s];
        a.x += ad.x; a.y += ad.y; a.z += ad.z; a.w += ad.w;
        a.x = (a.x > 0.f) ? a.x : NEG * a.x;
        a.y = (a.y > 0.f) ? a.y : NEG * a.y;
        a.z = (a.z > 0.f) ? a.z : NEG * a.z;
        a.w = (a.w > 0.f) ? a.w : NEG * a.w;
        attn4[i] = a;
        m.x = fmaxf(m.x, a.x); m.y = fmaxf(m.y, a.y);
        m.z = fmaxf(m.z, a.z); m.w = fmaxf(m.w, a.w);
    }
#pragma unroll
    for (int o = 16; o >= 1; o >>= 1) {
        m.x = fmaxf(m.x, __shfl_xor_sync(0xffffffffu, m.x, o));
        m.y = fmaxf(m.y, __shfl_xor_sync(0xffffffffu, m.y, o));
        m.z = fmaxf(m.z, __shfl_xor_sync(0xffffffffu, m.z, o));
        m.w = fmaxf(m.w, __shfl_xor_sync(0xffffffffu, m.w, o));
    }
    float4 den = make_float4(0.f, 0.f, 0.f, 0.f);
    for (int i = s0 + lane; i < s1; i += 32) {
        float4 a = attn4[i];
        a.x = __expf(a.x - m.x); a.y = __expf(a.y - m.y);
        a.z = __expf(a.z - m.z); a.w = __expf(a.w - m.w);
        attn4[i] = a;
        den.x += a.x; den.y += a.y; den.z += a.z; den.w += a.w;
    }
#pragma unroll
    for (int o = 16; o >= 1; o >>= 1) {
        den.x += __shfl_xor_sync(0xffffffffu, den.x, o);
        den.y += __shfl_xor_sync(0xffffffffu, den.y, o);
        den.z += __shfl_xor_sync(0xffffffffu, den.z, o);
        den.w += __shfl_xor_sync(0xffffffffu, den.w, o);
    }
    if (lane == 0)
        rden4[w] = make_float4(1.f / den.x, 1.f / den.y, 1.f / den.z, 1.f / den.w);
}

// ---------------- warp-per-dst segment softmax (H=1, layer 3) ----------------
__global__ void k_attnW1(const float* __restrict__ als, const float* __restrict__ ald,
                         float* __restrict__ attn, float* __restrict__ rden) {
    int w = (blockIdx.x * blockDim.x + threadIdx.x) >> 5;
    if (w >= NN) return;
    int lane = threadIdx.x & 31;
    int s0 = g_off[w], s1 = g_off[w + 1];
    float ad = ald[w];
    float m = -1e30f;
    for (int i = s0 + lane; i < s1; i += 32) {
        int s = g_csr[i];
        float a = als[s] + ad;
        a = (a > 0.f) ? a : NEG * a;
        attn[i] = a;
        m = fmaxf(m, a);
    }
#pragma unroll
    for (int o = 16; o >= 1; o >>= 1) m = fmaxf(m, __shfl_xor_sync(0xffffffffu, m, o));
    float den = 0.f;
    for (int i = s0 + lane; i < s1; i += 32) {
        float a = __expf(attn[i] - m);
        attn[i] = a;
        den += a;
    }
#pragma unroll
    for (int o = 16; o >= 1; o >>= 1) den += __shfl_xor_sync(0xffffffffu, den, o);
    if (lane == 0) rden[w] = 1.f / den;
}

// ---------------- bf16 aggregation gather: warp per dst, bf16 out ---------
__global__ void k_gather256(const __nv_bfloat16* __restrict__ hb,
                            const float* __restrict__ bias,
                            const float* __restrict__ attn, const float* __restrict__ rden,
                            __nv_bfloat16* __restrict__ out) {
    int w = (blockIdx.x * blockDim.x + threadIdx.x) >> 5;
    if (w >= NN) return;
    int lane = threadIdx.x & 31;
    int head = lane >> 3;
    int s0 = g_off[w], s1 = g_off[w + 1];
    float acc[8] = {0.f, 0.f, 0.f, 0.f, 0.f, 0.f, 0.f, 0.f};
    for (int i = s0; i < s1; i++) {
        int s = g_csr[i];
        float wt = attn[(size_t)i * 4 + head];
        const __nv_bfloat16* hr = hb + (size_t)s * HC + lane * 8;
        uint4 u = *(const uint4*)hr;
        float2 f0 = __bfloat1622float2(*(__nv_bfloat162*)&u.x);
        float2 f1 = __bfloat1622float2(*(__nv_bfloat162*)&u.y);
        float2 f2 = __bfloat1622float2(*(__nv_bfloat162*)&u.z);
        float2 f3 = __bfloat1622float2(*(__nv_bfloat162*)&u.w);
        acc[0] += wt * f0.x; acc[1] += wt * f0.y;
        acc[2] += wt * f1.x; acc[3] += wt * f1.y;
        acc[4] += wt * f2.x; acc[5] += wt * f2.y;
        acc[6] += wt * f3.x; acc[7] += wt * f3.y;
    }
    float rd = rden[w * 4 + head];
    float4 b0 = *(const float4*)(bias + lane * 8);
    float4 b1 = *(const float4*)(bias + lane * 8 + 4);
    float v[8];
    v[0] = fmaxf(acc[0] * rd + b0.x, 0.f); v[1] = fmaxf(acc[1] * rd + b0.y, 0.f);
    v[2] = fmaxf(acc[2] * rd + b0.z, 0.f); v[3] = fmaxf(acc[3] * rd + b0.w, 0.f);
    v[4] = fmaxf(acc[4] * rd + b1.x, 0.f); v[5] = fmaxf(acc[5] * rd + b1.y, 0.f);
    v[6] = fmaxf(acc[6] * rd + b1.z, 0.f); v[7] = fmaxf(acc[7] * rd + b1.w, 0.f);
    uint4 u;
    *(__nv_bfloat162*)&u.x = __float22bfloat162_rn(make_float2(v[0], v[1]));
    *(__nv_bfloat162*)&u.y = __float22bfloat162_rn(make_float2(v[2], v[3]));
    *(__nv_bfloat162*)&u.z = __float22bfloat162_rn(make_float2(v[4], v[5]));
    *(__nv_bfloat162*)&u.w = __float22bfloat162_rn(make_float2(v[6], v[7]));
    *(uint4*)(out + (size_t)w * HC + lane * 8) = u;
}

// layer 3: gather + bias + log_softmax fused (fp32 h)
__global__ void k_gather40(const float* __restrict__ h, const float* __restrict__ bias,
                           const float* __restrict__ attn, const float* __restrict__ rden,
                           float* __restrict__ out) {
    int w = (blockIdx.x * blockDim.x + threadIdx.x) >> 5;
    if (w >= NN) return;
    int lane = threadIdx.x & 31;
    int s0 = g_off[w], s1 = g_off[w + 1];
    float a0 = 0.f, a1 = 0.f;
    for (int i = s0; i < s1; i++) {
        int s = g_csr[i];
        float wt = attn[i];
        const float* hr = h + (size_t)s * OUTC;
        a0 += wt * hr[lane];
        if (lane < 8) a1 += wt * hr[32 + lane];
    }
    float rd = rden[w];
    float v0 = a0 * rd + bias[lane];
    float v1 = (lane < 8) ? (a1 * rd + bias[32 + lane]) : -1e30f;
    float mx = fmaxf(v0, v1);
#pragma unroll
    for (int o = 16; o >= 1; o >>= 1) mx = fmaxf(mx, __shfl_xor_sync(0xffffffffu, mx, o));
    float se = __expf(v0 - mx) + ((lane < 8) ? __expf(v1 - mx) : 0.f);
#pragma unroll
    for (int o = 16; o >= 1; o >>= 1) se += __shfl_xor_sync(0xffffffffu, se, o);
    float lse = mx + __logf(se);
    float* orow = out + (size_t)w * OUTC;
    orow[lane] = v0 - lse;
    if (lane < 8) orow[32 + lane] = v1 - lse;
}

// ---------------- launch ----------------
extern "C" void kernel_launch(void* const* d_in, const int* in_sizes, int n_in,
                              void* d_out, int out_size) {
    const float* x   = (const float*)d_in[0];
    const void*  ei  = d_in[1];
    const float* W1  = (const float*)d_in[2];
    const float* as1 = (const float*)d_in[3];
    const float* ad1 = (const float*)d_in[4];
    const float* b1  = (const float*)d_in[5];
    const float* W2  = (const float*)d_in[6];
    const float* as2 = (const float*)d_in[7];
    const float* ad2 = (const float*)d_in[8];
    const float* b2  = (const float*)d_in[9];
    const float* W3  = (const float*)d_in[10];
    const float* as3 = (const float*)d_in[11];
    const float* ad3 = (const float*)d_in[12];
    const float* b3  = (const float*)d_in[13];
    float* out = (float*)d_out;

    __nv_bfloat16 *xh, *bufHh, *bufAh;
    float *bufH3, *als, *ald, *attn, *rden;
    cudaGetSymbolAddress((void**)&xh,    g_xh);
    cudaGetSymbolAddress((void**)&bufHh, g_bufHh);
    cudaGetSymbolAddress((void**)&bufAh, g_bufAh);
    cudaGetSymbolAddress((void**)&bufH3, g_bufH3);
    cudaGetSymbolAddress((void**)&als,   g_als);
    cudaGetSymbolAddress((void**)&ald,   g_ald);
    cudaGetSymbolAddress((void**)&attn,  g_attn);
    cudaGetSymbolAddress((void**)&rden,  g_rden);

    const int TB = 256;
    int nodeBlocks = (NN + TB - 1) / TB;
    int warpBlocks = (NN * 32 + TB - 1) / TB;
    int edgeBlocks = (ET + TB - 1) / TB;
    int scanBlocks = (NN + SB - 1) / SB;
    int cvtBlocks  = (NN * INC / 8 + TB - 1) / TB;

    // ---- CSR build + x conversion ----
    k_detect<<<1, 256>>>((const int*)ei);
    k_zero<<<nodeBlocks, TB>>>();
    k_hist<<<edgeBlocks, TB>>>(ei);
    k_cvt<<<cvtBlocks, TB>>>(x, xh, NN * INC / 8);
    k_scan1<<<scanBlocks, SB>>>();
    k_scan2<<<1, 32>>>(scanBlocks);
    k_scan3<<<scanBlocks, SB>>>();
    k_scatter<<<edgeBlocks, TB>>>(ei);

    dim3 g1(4, (NN + 127) / 128);     // (4, 391)
    dim3 g3(1, (NN + 127) / 128);     // (1, 391)

    // ---- Layer 1 ----
    k_gemmb<HC, 4, __nv_bfloat16><<<g1, 256>>>(xh, W1, bufHh, as1, ad1, als, ald, NN, INC);
    k_attnW4<<<warpBlocks, TB>>>((const float4*)als, (const float4*)ald,
                                 (float4*)attn, (float4*)rden);
    k_gather256<<<warpBlocks, TB>>>(bufHh, b1, attn, rden, bufAh);

    // ---- Layer 2 ----
    k_gemmb<HC, 4, __nv_bfloat16><<<g1, 256>>>(bufAh, W2, bufHh, as2, ad2, als, ald, NN, HC);
    k_attnW4<<<warpBlocks, TB>>>((const float4*)als, (const float4*)ald,
                                 (float4*)attn, (float4*)rden);
    k_gather256<<<warpBlocks, TB>>>(bufHh, b2, attn, rden, bufAh);

    // ---- Layer 3 ----
    k_gemmb<OUTC, 1, float><<<g3, 256>>>(bufAh, W3, bufH3, as3, ad3, als, ald, NN, HC);
    k_attnW1<<<warpBlocks, TB>>>(als, ald, attn, rden);
    k_gather40<<<warpBlocks, TB>>>(bufH3, b3, attn, rden, out);
}